// round 2
// baseline (speedup 1.0000x reference)
#include <cuda_runtime.h>
#include <cuda_bf16.h>

#define BQ 4
#define NQ 2048
#define TILE 128
#define TT (NQ / TILE)                 /* 16 tiles per batch row */
#define PAIRS_B (TT * (TT + 1) / 2)    /* 136 tile pairs (j >= i) */
#define NBLOCKS (BQ * PAIRS_B)         /* 544 blocks */

struct __align__(16) Pack { float4 v[5]; };
// v0 = (x, y, z, sx)
// v1 = (sy, sz, vx, vy)
// v2 = (vz, c0x, c0y, c0z)   c_j = column j of R (R0j,R1j,R2j)
// v3 = (c1x, c1y, c1z, c2x)
// v4 = (c2y, c2z, 0, 0)

__device__ Pack   g_pack[BQ * NQ];
__device__ double g_acc[2];

__global__ void prep_kernel(const float* __restrict__ xyz,
                            const float* __restrict__ scl,
                            const float* __restrict__ rot,
                            const float* __restrict__ vel) {
    int i = blockIdx.x * blockDim.x + threadIdx.x;
    if (i == 0) { g_acc[0] = 0.0; g_acc[1] = 0.0; }
    if (i >= BQ * NQ) return;

    float qw = rot[4*i+0], qx = rot[4*i+1], qy = rot[4*i+2], qz = rot[4*i+3];
    // R columns (R[row][col]); u_j = sum_i d_i * R[i][j]
    float c0x = 1.f - 2.f*(qy*qy + qz*qz);   // R00
    float c0y = 2.f*(qx*qy + qz*qw);         // R10
    float c0z = 2.f*(qx*qz - qy*qw);         // R20
    float c1x = 2.f*(qx*qy - qz*qw);         // R01
    float c1y = 1.f - 2.f*(qx*qx + qz*qz);   // R11
    float c1z = 2.f*(qy*qz + qx*qw);         // R21
    float c2x = 2.f*(qx*qz + qy*qw);         // R02
    float c2y = 2.f*(qy*qz - qx*qw);         // R12
    float c2z = 1.f - 2.f*(qx*qx + qy*qy);   // R22

    Pack p;
    p.v[0] = make_float4(xyz[3*i+0], xyz[3*i+1], xyz[3*i+2], scl[3*i+0]);
    p.v[1] = make_float4(scl[3*i+1], scl[3*i+2], vel[3*i+0], vel[3*i+1]);
    p.v[2] = make_float4(vel[3*i+2], c0x, c0y, c0z);
    p.v[3] = make_float4(c1x, c1y, c1z, c2x);
    p.v[4] = make_float4(c2y, c2z, 0.f, 0.f);
    g_pack[i] = p;
}

// Shared inner-pair evaluation. Deferred normalization:
//   r1 + r2 - dist = rinv*(sA + sB) - d2*rinv  =>  overlap = rinv * relu(sA+sB-d2)
//   relu(-v.u) = rinv * relu(-v.d)            (rinv > 0)
struct Own {
    float nx, ny, nz, nsx, nsy, nsz, nvx, nvy, nvz;
    float c0x, c0y, c0z, c1x, c1y, c1z, c2x, c2y, c2z;
};

__device__ __forceinline__ void pair_body(const Own& o,
                                          const float4& w0, const float4& w1,
                                          const float4& w2, const float4& w3,
                                          const float4& w4,
                                          float& sp, float& ms) {
    float dx = o.nx - w0.x, dy = o.ny - w0.y, dz = o.nz - w0.z;
    float d2 = fmaf(dx, dx, fmaf(dy, dy, fmaf(dz, dz, 1e-8f)));
    float rinv = rsqrtf(d2);

    // A = (d @ R_n) * s_m   (s_m = w0.w, w1.x, w1.y)
    float a0 = fmaf(dx, o.c0x, fmaf(dy, o.c0y, dz * o.c0z)) * w0.w;
    float a1 = fmaf(dx, o.c1x, fmaf(dy, o.c1y, dz * o.c1z)) * w1.x;
    float a2 = fmaf(dx, o.c2x, fmaf(dy, o.c2y, dz * o.c2z)) * w1.y;
    float A2 = fmaf(a0, a0, fmaf(a1, a1, a2 * a2));

    // B = (d @ R_m) * s_n   (R_m columns from w2..w4)
    float b0 = fmaf(dx, w2.y, fmaf(dy, w2.z, dz * w2.w)) * o.nsx;
    float b1 = fmaf(dx, w3.x, fmaf(dy, w3.y, dz * w3.z)) * o.nsy;
    float b2 = fmaf(dx, w3.w, fmaf(dy, w4.x, dz * w4.y)) * o.nsz;
    float B2 = fmaf(b0, b0, fmaf(b1, b1, b2 * b2));

    // sqrt via x * rsqrt(max(x,eps)); x=0 -> 0 * big = 0 (exact)
    float sA = A2 * rsqrtf(fmaxf(A2, 1e-30f));
    float sB = B2 * rsqrtf(fmaxf(B2, 1e-30f));

    float ovl = fmaxf(sA + sB - d2, 0.f);      // overlap / rinv
    float ov  = ovl * rinv;
    sp = __fdividef(ov * ov, fmaf(0.1f, ov, 1.f));

    float vdx = o.nvx - w1.z, vdy = o.nvy - w1.w, vdz = o.nvz - w2.x;
    float vd  = fmaf(vdx, dx, fmaf(vdy, dy, vdz * dz));
    float neg = fmaxf(-vd, 0.f);               // relu(-v.d)
    ms = (ovl * neg) * (rinv * rinv);
}

__global__ __launch_bounds__(TILE) void pair_kernel() {
    __shared__ float4 sm[TILE][5];

    int blk  = blockIdx.x;
    int b    = blk / PAIRS_B;
    int pidx = blk - b * PAIRS_B;

    // decode (ti, tj) with tj >= ti from triangular index
    int ti = 0, rem = pidx;
    while (rem >= TT - ti) { rem -= TT - ti; ti++; }
    int tj = ti + rem;

    int tid  = threadIdx.x;
    int base = b * NQ;

    // stage tile j into shared memory
    {
        const Pack* pm = &g_pack[base + tj * TILE + tid];
        sm[tid][0] = pm->v[0];
        sm[tid][1] = pm->v[1];
        sm[tid][2] = pm->v[2];
        sm[tid][3] = pm->v[3];
        sm[tid][4] = pm->v[4];
    }
    __syncthreads();

    // own point (row n in tile i)
    Pack pn = g_pack[base + ti * TILE + tid];
    Own o;
    o.nx = pn.v[0].x;  o.ny = pn.v[0].y;  o.nz = pn.v[0].z;
    o.nsx = pn.v[0].w; o.nsy = pn.v[1].x; o.nsz = pn.v[1].y;
    o.nvx = pn.v[1].z; o.nvy = pn.v[1].w; o.nvz = pn.v[2].x;
    o.c0x = pn.v[2].y; o.c0y = pn.v[2].z; o.c0z = pn.v[2].w;
    o.c1x = pn.v[3].x; o.c1y = pn.v[3].y; o.c1z = pn.v[3].z;
    o.c2x = pn.v[3].w; o.c2y = pn.v[4].x; o.c2z = pn.v[4].y;

    float acc_sp = 0.f, acc_ms = 0.f;

    if (ti != tj) {
        // off-diagonal tile pair: every m counts
#pragma unroll 4
        for (int mm = 0; mm < TILE; mm++) {
            float sp, ms;
            pair_body(o, sm[mm][0], sm[mm][1], sm[mm][2], sm[mm][3], sm[mm][4],
                      sp, ms);
            acc_sp += sp;
            acc_ms += ms;
        }
    } else {
        // diagonal tile: unordered pairs only (mm > tid); others contribute 0
#pragma unroll 4
        for (int mm = 0; mm < TILE; mm++) {
            float sp, ms;
            pair_body(o, sm[mm][0], sm[mm][1], sm[mm][2], sm[mm][3], sm[mm][4],
                      sp, ms);
            bool take = (mm > tid);
            acc_sp += take ? sp : 0.f;
            acc_ms += take ? ms : 0.f;
        }
    }

    // warp reduce
#pragma unroll
    for (int off = 16; off > 0; off >>= 1) {
        acc_sp += __shfl_down_sync(0xffffffffu, acc_sp, off);
        acc_ms += __shfl_down_sync(0xffffffffu, acc_ms, off);
    }

    __shared__ float red[2][TILE / 32];
    int wid = tid >> 5, lane = tid & 31;
    if (lane == 0) { red[0][wid] = acc_sp; red[1][wid] = acc_ms; }
    __syncthreads();

    if (tid == 0) {
        double s = 0.0, m = 0.0;
#pragma unroll
        for (int w = 0; w < TILE / 32; w++) {
            s += (double)red[0][w];
            m += (double)red[1][w];
        }
        atomicAdd(&g_acc[0], s);
        atomicAdd(&g_acc[1], m);
    }
}

__global__ void final_kernel(float* __restrict__ out) {
    const double denom = (double)BQ * (double)NQ * (double)NQ;
    // each unordered pair stands for 2 directed pairs; diagonal contributes 0
    double sp = 2.0 * g_acc[0];
    double ms = 2.0 * g_acc[1];
    out[0] = (float)(sp / denom + 0.1 * (ms / denom));
}

extern "C" void kernel_launch(void* const* d_in, const int* in_sizes, int n_in,
                              void* d_out, int out_size) {
    const float* xyz = (const float*)d_in[0];
    const float* scl = (const float*)d_in[1];
    const float* rot = (const float*)d_in[2];
    const float* vel = (const float*)d_in[3];

    prep_kernel<<<(BQ * NQ + 255) / 256, 256>>>(xyz, scl, rot, vel);
    pair_kernel<<<NBLOCKS, TILE>>>();
    final_kernel<<<1, 1>>>((float*)d_out);
}

// round 5
// speedup vs baseline: 1.1308x; 1.1308x over previous
#include <cuda_runtime.h>
#include <cuda_bf16.h>

#define BQ 4
#define NQ 2048
#define TILE 128
#define TT (NQ / TILE)                 /* 16 tiles per batch row */
#define PAIRS_B (TT * (TT + 1) / 2)    /* 136 tile pairs (j >= i) */
#define NBLOCKS (BQ * PAIRS_B)         /* 544 blocks */

typedef unsigned long long ull;

__device__ float2 g_part[NBLOCKS];     // per-block partials; fully overwritten each launch

// ---------- packed f32x2 helpers (sm_103a) ----------
__device__ __forceinline__ ull f2pk(float a, float b) {
    ull r; asm("mov.b64 %0, {%1, %2};" : "=l"(r) : "f"(a), "f"(b)); return r;
}
__device__ __forceinline__ ull bcast(float a) { return f2pk(a, a); }
__device__ __forceinline__ void unpk(ull v, float& a, float& b) {
    asm("mov.b64 {%0, %1}, %2;" : "=f"(a), "=f"(b) : "l"(v));
}
__device__ __forceinline__ ull fma2(ull a, ull b, ull c) {
    ull d; asm("fma.rn.f32x2 %0, %1, %2, %3;" : "=l"(d) : "l"(a), "l"(b), "l"(c)); return d;
}
__device__ __forceinline__ ull add2(ull a, ull b) {
    ull d; asm("add.rn.f32x2 %0, %1, %2;" : "=l"(d) : "l"(a), "l"(b)); return d;
}
__device__ __forceinline__ ull mul2(ull a, ull b) {
    ull d; asm("mul.rn.f32x2 %0, %1, %2;" : "=l"(d) : "l"(a), "l"(b)); return d;
}
// ---------- MUFU approx ----------
__device__ __forceinline__ float rsq_a(float x) { float r; asm("rsqrt.approx.f32 %0, %1;" : "=f"(r) : "f"(x)); return r; }
__device__ __forceinline__ float sqrt_a(float x){ float r; asm("sqrt.approx.f32 %0, %1;"  : "=f"(r) : "f"(x)); return r; }
__device__ __forceinline__ float rcp_a(float x) { float r; asm("rcp.approx.f32 %0, %1;"   : "=f"(r) : "f"(x)); return r; }

// quaternion (w,x,y,z) -> rotation matrix columns c[j]=(R0j,R1j,R2j), no normalization
__device__ __forceinline__ void quat_cols(float qw, float qx, float qy, float qz, float c[9]) {
    c[0] = 1.f - 2.f*(qy*qy + qz*qz);   // R00
    c[1] = 2.f*(qx*qy + qz*qw);         // R10
    c[2] = 2.f*(qx*qz - qy*qw);         // R20
    c[3] = 2.f*(qx*qy - qz*qw);         // R01
    c[4] = 1.f - 2.f*(qx*qx + qz*qz);   // R11
    c[5] = 2.f*(qy*qz + qx*qw);         // R21
    c[6] = 2.f*(qx*qz + qy*qw);         // R02
    c[7] = 2.f*(qy*qz - qx*qw);         // R12
    c[8] = 1.f - 2.f*(qx*qx + qy*qy);   // R22
}

struct OwnP {
    ull x, y, z;          // own position (broadcast)
    ull s2x, s2y, s2z;    // own scale^2
    ull vx, vy, vz;       // own velocity
    ull c[9];             // own rotmat columns
};

// SoA smem field indices for tile j:
// 0..2  : -x, -y, -z          3..5 : sx^2, sy^2, sz^2
// 6..8  : -vx, -vy, -vz       9..17: c0x,c0y,c0z,c1x,c1y,c1z,c2x,c2y,c2z
template<bool DIAG>
__device__ __forceinline__ void inner_loop(const OwnP& o, const float (*sm)[TILE],
                                           int tid, float& accs, float& accm) {
    const ull E8  = bcast(1e-8f);
    const ull E30 = bcast(1e-30f);
#pragma unroll 2
    for (int mm = 0; mm < TILE; mm += 2) {
#define LP(f) (*(const ull*)&sm[f][mm])
        ull dx = add2(o.x, LP(0));
        ull dy = add2(o.y, LP(1));
        ull dz = add2(o.z, LP(2));
        ull d2 = fma2(dx, dx, fma2(dy, dy, fma2(dz, dz, E8)));

        // u = d . R_n (own rotation), A2 = sum s2_m,j * u_j^2 + eps
        ull u0 = fma2(dx, o.c[0], fma2(dy, o.c[1], mul2(dz, o.c[2])));
        ull u1 = fma2(dx, o.c[3], fma2(dy, o.c[4], mul2(dz, o.c[5])));
        ull u2 = fma2(dx, o.c[6], fma2(dy, o.c[7], mul2(dz, o.c[8])));
        ull A2 = fma2(LP(3), mul2(u0, u0),
                 fma2(LP(4), mul2(u1, u1),
                 fma2(LP(5), mul2(u2, u2), E30)));

        // v = d . R_m (smem rotation), B2 = sum s2_n,j * v_j^2 + eps
        ull v0 = fma2(dx, LP(9),  fma2(dy, LP(10), mul2(dz, LP(11))));
        ull v1 = fma2(dx, LP(12), fma2(dy, LP(13), mul2(dz, LP(14))));
        ull v2 = fma2(dx, LP(15), fma2(dy, LP(16), mul2(dz, LP(17))));
        ull B2 = fma2(o.s2x, mul2(v0, v0),
                 fma2(o.s2y, mul2(v1, v1),
                 fma2(o.s2z, mul2(v2, v2), E30)));

        // v_rel . d  (unnormalized)
        ull wx = add2(o.vx, LP(6));
        ull wy = add2(o.vy, LP(7));
        ull wz = add2(o.vz, LP(8));
        ull vd = fma2(wx, dx, fma2(wy, dy, mul2(wz, dz)));
#undef LP
        float d2a, d2b, A2a, A2b, B2a, B2b, vda, vdb;
        unpk(d2, d2a, d2b); unpk(A2, A2a, A2b);
        unpk(B2, B2a, B2b); unpk(vd, vda, vdb);

        // scalar tail, half 0 (point mm)
        {
            float rinv = rsq_a(d2a);
            float ovl  = fmaxf(sqrt_a(A2a) + sqrt_a(B2a) - d2a, 0.f);  // overlap/rinv
            float ov   = ovl * rinv;
            float sp   = ov * ov * rcp_a(fmaf(0.1f, ov, 1.f));
            float ms   = (ovl * fmaxf(-vda, 0.f)) * (rinv * rinv);
            if (DIAG) { bool take = mm > tid; sp = take ? sp : 0.f; ms = take ? ms : 0.f; }
            accs += sp; accm += ms;
        }
        // scalar tail, half 1 (point mm+1)
        {
            float rinv = rsq_a(d2b);
            float ovl  = fmaxf(sqrt_a(A2b) + sqrt_a(B2b) - d2b, 0.f);
            float ov   = ovl * rinv;
            float sp   = ov * ov * rcp_a(fmaf(0.1f, ov, 1.f));
            float ms   = (ovl * fmaxf(-vdb, 0.f)) * (rinv * rinv);
            if (DIAG) { bool take = (mm + 1) > tid; sp = take ? sp : 0.f; ms = take ? ms : 0.f; }
            accs += sp; accm += ms;
        }
    }
}

__global__ __launch_bounds__(TILE) void pair_kernel(const float* __restrict__ xyz,
                                                    const float* __restrict__ scl,
                                                    const float* __restrict__ rot,
                                                    const float* __restrict__ vel) {
    __shared__ __align__(16) float sm[18][TILE];

    int blk  = blockIdx.x;
    int b    = blk / PAIRS_B;
    int pidx = blk - b * PAIRS_B;
    int ti = 0, rem = pidx;
    while (rem >= TT - ti) { rem -= TT - ti; ti++; }
    int tj = ti + rem;

    int tid  = threadIdx.x;
    int base = b * NQ;

    // stage tile j into SoA smem (fused "prep")
    {
        int g = base + tj * TILE + tid;
        float4 q = ((const float4*)rot)[g];
        float c[9];
        quat_cols(q.x, q.y, q.z, q.w, c);
        sm[0][tid] = -xyz[3*g+0];  sm[1][tid] = -xyz[3*g+1];  sm[2][tid] = -xyz[3*g+2];
        float s0 = scl[3*g+0], s1 = scl[3*g+1], s2 = scl[3*g+2];
        sm[3][tid] = s0*s0;        sm[4][tid] = s1*s1;        sm[5][tid] = s2*s2;
        sm[6][tid] = -vel[3*g+0];  sm[7][tid] = -vel[3*g+1];  sm[8][tid] = -vel[3*g+2];
#pragma unroll
        for (int k = 0; k < 9; k++) sm[9 + k][tid] = c[k];
    }

    // own point (row n in tile i), packed-broadcast constants
    OwnP o;
    {
        int g = base + ti * TILE + tid;
        float4 q = ((const float4*)rot)[g];
        float c[9];
        quat_cols(q.x, q.y, q.z, q.w, c);
        o.x = bcast(xyz[3*g+0]); o.y = bcast(xyz[3*g+1]); o.z = bcast(xyz[3*g+2]);
        float s0 = scl[3*g+0], s1 = scl[3*g+1], s2 = scl[3*g+2];
        o.s2x = bcast(s0*s0); o.s2y = bcast(s1*s1); o.s2z = bcast(s2*s2);
        o.vx = bcast(vel[3*g+0]); o.vy = bcast(vel[3*g+1]); o.vz = bcast(vel[3*g+2]);
#pragma unroll
        for (int k = 0; k < 9; k++) o.c[k] = bcast(c[k]);
    }
    __syncthreads();

    float accs = 0.f, accm = 0.f;
    if (ti != tj) inner_loop<false>(o, sm, tid, accs, accm);
    else          inner_loop<true >(o, sm, tid, accs, accm);

    // block reduce
#pragma unroll
    for (int off = 16; off > 0; off >>= 1) {
        accs += __shfl_down_sync(0xffffffffu, accs, off);
        accm += __shfl_down_sync(0xffffffffu, accm, off);
    }
    __shared__ float red[2][TILE / 32];
    int wid = tid >> 5, lane = tid & 31;
    if (lane == 0) { red[0][wid] = accs; red[1][wid] = accm; }
    __syncthreads();
    if (tid == 0) {
        float s = 0.f, m = 0.f;
#pragma unroll
        for (int w = 0; w < TILE / 32; w++) { s += red[0][w]; m += red[1][w]; }
        g_part[blk] = make_float2(s, m);
    }
}

__global__ void final_kernel(float* __restrict__ out) {
    int tid = threadIdx.x;
    double s = 0.0, m = 0.0;
    for (int i = tid; i < NBLOCKS; i += 256) {
        float2 p = g_part[i];
        s += (double)p.x;
        m += (double)p.y;
    }
#pragma unroll
    for (int off = 16; off > 0; off >>= 1) {
        s += __shfl_down_sync(0xffffffffu, s, off);
        m += __shfl_down_sync(0xffffffffu, m, off);
    }
    __shared__ double rs[8], rm[8];
    int wid = tid >> 5, lane = tid & 31;
    if (lane == 0) { rs[wid] = s; rm[wid] = m; }
    __syncthreads();
    if (tid == 0) {
        double S = 0.0, M = 0.0;
#pragma unroll
        for (int w = 0; w < 8; w++) { S += rs[w]; M += rm[w]; }
        const double denom = (double)BQ * (double)NQ * (double)NQ;
        // each unordered pair stands for 2 directed pairs; diagonal contributes 0
        out[0] = (float)((2.0 * S + 0.2 * M) / denom);
    }
}

extern "C" void kernel_launch(void* const* d_in, const int* in_sizes, int n_in,
                              void* d_out, int out_size) {
    const float* xyz = (const float*)d_in[0];
    const float* scl = (const float*)d_in[1];
    const float* rot = (const float*)d_in[2];
    const float* vel = (const float*)d_in[3];

    pair_kernel<<<NBLOCKS, TILE>>>(xyz, scl, rot, vel);
    final_kernel<<<1, 256>>>((float*)d_out);
}